// round 13
// baseline (speedup 1.0000x reference)
#include <cuda_runtime.h>
#include <cuda_bf16.h>
#include <math.h>
#include <stdint.h>

#define N_NODES  100000
#define N_EDGES  1600000
#define D        128
#define N_GRAPHS 512
#define N_CLASS  10
#define BN_EPS   1e-5f

#define NT   ((size_t)N_NODES * D)      // 12.8M floats
#define PAD_M 100032                    // 1563 * 64

#define SCAN_BLK 512
#define NSCAN    ((N_NODES + SCAN_BLK - 1) / SCAN_BLK)   // 196

// ---------------------------------------------------------------------------
// Scratch (allocation-free: __device__ globals)
// ---------------------------------------------------------------------------
__device__ float g_bufB[NT];            // z1 (fp32)
__device__ float g_pooled[N_GRAPHS * D];
__device__ float g_scale[D];
__device__ float g_shift[D];

__device__ int g_deg[N_NODES];
__device__ int g_rowstart[N_NODES];
__device__ int g_cursor[N_NODES];
__device__ int g_csrsrc[N_EDGES];
__device__ int g_total;

// W split into bf16 hi/lo, n-major ([n][k]) — B operand for mma row.col
__device__ __nv_bfloat16 g_Whi[2][D * D];
__device__ __nv_bfloat16 g_Wlo[2][D * D];

// ---------------------------------------------------------------------------
// helpers
// ---------------------------------------------------------------------------
__device__ __forceinline__ uint32_t smem_to_u32(const void* p) {
    uint32_t a;
    asm("{ .reg .u64 t; cvta.to.shared.u64 t, %1; cvt.u32.u64 %0, t; }"
        : "=r"(a) : "l"(p));
    return a;
}
__device__ __forceinline__ void ldm_x4(uint32_t* r, uint32_t addr) {
    asm volatile("ldmatrix.sync.aligned.m8n8.x4.shared.b16 {%0,%1,%2,%3}, [%4];"
                 : "=r"(r[0]), "=r"(r[1]), "=r"(r[2]), "=r"(r[3]) : "r"(addr));
}
__device__ __forceinline__ void mma_bf16(float* c, const uint32_t* a,
                                         const uint32_t* b) {
    asm volatile(
        "mma.sync.aligned.m16n8k16.row.col.f32.bf16.bf16.f32 "
        "{%0,%1,%2,%3}, {%4,%5,%6,%7}, {%8,%9}, {%0,%1,%2,%3};"
        : "+f"(c[0]), "+f"(c[1]), "+f"(c[2]), "+f"(c[3])
        : "r"(a[0]), "r"(a[1]), "r"(a[2]), "r"(a[3]), "r"(b[0]), "r"(b[1]));
}
__device__ __forceinline__ uint32_t pkbf2(float a, float b) {
    __nv_bfloat162 t = __floats2bfloat162_rn(a, b);
    return *reinterpret_cast<uint32_t*>(&t);
}
__device__ __forceinline__ void cp16(uint32_t smem, const void* g) {
    asm volatile("cp.async.cg.shared.global [%0], [%1], 16;"
                 :: "r"(smem), "l"(g) : "memory");
}
#define CP_COMMIT() asm volatile("cp.async.commit_group;" ::: "memory")
#define CP_WAIT0()  asm volatile("cp.async.wait_group 0;" ::: "memory")

// ---------------------------------------------------------------------------
// prep0: zero deg/pooled/total + W hi/lo split (one kernel)
// ---------------------------------------------------------------------------
__global__ void prep0(const float* __restrict__ W1, const float* __restrict__ W2) {
    int i = blockIdx.x * blockDim.x + threadIdx.x;
    if (i < N_NODES) g_deg[i] = 0;
    if (i == 0) g_total = 0;
    if (i < N_GRAPHS * D) g_pooled[i] = 0.f;
    if (i < 2 * D * D) {
        int layer = i >> 14;
        int k = (i >> 7) & 127;
        int n = i & 127;
        float v = (layer ? W2 : W1)[k * D + n];
        __nv_bfloat16 hi = __float2bfloat16_rn(v);
        float lo = v - __bfloat162float(hi);
        g_Whi[layer][n * D + k] = hi;
        g_Wlo[layer][n * D + k] = __float2bfloat16_rn(lo);
    }
}

__global__ void hist_deg(const int* __restrict__ dst) {
    int e = blockIdx.x * blockDim.x + threadIdx.x;
    if (e < N_EDGES) atomicAdd(&g_deg[dst[e]], 1);
}

// Block-local inclusive scan + one global atomic per block. Segment order
// across blocks is arbitrary — irrelevant for gather correctness.
__global__ __launch_bounds__(SCAN_BLK) void assign_rows() {
    __shared__ int s[SCAN_BLK];
    __shared__ int sbase;
    int t = threadIdx.x;
    int i = blockIdx.x * SCAN_BLK + t;
    int v = (i < N_NODES) ? g_deg[i] : 0;
    s[t] = v;
    __syncthreads();
    #pragma unroll
    for (int off = 1; off < SCAN_BLK; off <<= 1) {
        int add = (t >= off) ? s[t - off] : 0;
        __syncthreads();
        s[t] += add;
        __syncthreads();
    }
    if (t == SCAN_BLK - 1) sbase = atomicAdd(&g_total, s[t]);
    __syncthreads();
    if (i < N_NODES) {
        int rs = sbase + s[t] - v;
        g_rowstart[i] = rs;
        g_cursor[i] = rs;
    }
}

__global__ void scatter_csr(const int* __restrict__ src,
                            const int* __restrict__ dst) {
    int e = blockIdx.x * blockDim.x + threadIdx.x;
    if (e < N_EDGES) {
        int pos = atomicAdd(&g_cursor[dst[e]], 1);
        g_csrsrc[pos] = src[e];
    }
}

// ---------------------------------------------------------------------------
// Fused layer: CSR gather aggregation (+self loop) -> bf16 hi/lo SMEM A tiles
// -> mma.sync split-3 GEMM -> epilogue.
// Block: 64 rows x 128 cols, 256 thr = 8 warps (2m x 4n), warp tile m32 x n32.
// LAYER 0: gather x;      epilogue relu(D+b1) -> g_bufB
// LAYER 1: gather g_bufB; epilogue (D+b2) segment-pool -> g_pooled
// ---------------------------------------------------------------------------
#define TSTRIDE 272
#define SM_AHI 0
#define SM_ALO 17408
#define SM_BHI 34816
#define SM_BLO 69632
#define SM_IDX 104448
#define SMEM_MMA (104448 + 512)

template<int LAYER>
__global__ __launch_bounds__(256, 2)
void fused_layer(const float* __restrict__ hext,
                 const __nv_bfloat16* __restrict__ Whi,
                 const __nv_bfloat16* __restrict__ Wlo,
                 const float* __restrict__ bias,
                 const int* __restrict__ idx) {
    extern __shared__ __align__(16) char sbp[];
    uint32_t sb = smem_to_u32(sbp);

    int tid  = threadIdx.x;
    int wid  = tid >> 5;
    int lane = tid & 31;
    int row0 = blockIdx.x * 64;
    int mr = (wid >> 2) * 32;            // warp row base (0,32)
    int nc = (wid & 3) * 32;             // warp col base (0,32,64,96)

    // ---- stage B hi/lo (128 rows x 256B each) via cp.async ----
    #pragma unroll
    for (int q = 0; q < 8; q++) {
        int e = tid + q * 256;           // 0..2047
        int row = e >> 4;
        int ch  = e & 15;
        cp16(sb + SM_BHI + row * TSTRIDE + ch * 16, Whi + row * D + ch * 8);
        cp16(sb + SM_BLO + row * TSTRIDE + ch * 16, Wlo + row * D + ch * 8);
    }
    CP_COMMIT();

    // ---- gather + split A: warp w handles local rows w*8..w*8+7 ----
    const float4* h4 = (const float4*)((LAYER == 0) ? hext : (const float*)g_bufB);
    #pragma unroll 1
    for (int q = 0; q < 8; q++) {
        int nl = wid * 8 + q;            // local row 0..63
        int n  = row0 + nl;
        float4 acc, acc2;
        if (n < N_NODES) {
            acc  = __ldg(h4 + (size_t)n * 32 + lane);   // self loop
            acc2 = make_float4(0.f, 0.f, 0.f, 0.f);
            int s0 = __ldg(g_rowstart + n);
            int e0 = s0 + __ldg(g_deg + n);
            for (int base = s0; base < e0; base += 32) {
                int cnt = min(32, e0 - base);
                int sv = (lane < cnt) ? __ldg(g_csrsrc + base + lane) : 0;
                int j = 0;
                for (; j + 1 < cnt; j += 2) {
                    int sa = __shfl_sync(0xffffffffu, sv, j);
                    int sbx = __shfl_sync(0xffffffffu, sv, j + 1);
                    float4 va = __ldg(h4 + (size_t)sa * 32 + lane);
                    float4 vb = __ldg(h4 + (size_t)sbx * 32 + lane);
                    acc.x += va.x;  acc.y += va.y;  acc.z += va.z;  acc.w += va.w;
                    acc2.x += vb.x; acc2.y += vb.y; acc2.z += vb.z; acc2.w += vb.w;
                }
                if (j < cnt) {
                    int sa = __shfl_sync(0xffffffffu, sv, j);
                    float4 va = __ldg(h4 + (size_t)sa * 32 + lane);
                    acc.x += va.x; acc.y += va.y; acc.z += va.z; acc.w += va.w;
                }
            }
            acc.x += acc2.x; acc.y += acc2.y; acc.z += acc2.z; acc.w += acc2.w;
        } else {
            acc = make_float4(0.f, 0.f, 0.f, 0.f);
        }
        float f[4] = {acc.x, acc.y, acc.z, acc.w};
        float fh[4], fl[4];
        #pragma unroll
        for (int e = 0; e < 4; e++) {
            __nv_bfloat16 h = __float2bfloat16_rn(f[e]);
            fh[e] = __bfloat162float(h);
            fl[e] = f[e] - fh[e];
        }
        *(uint2*)(sbp + SM_AHI + nl * TSTRIDE + lane * 8) =
            make_uint2(pkbf2(fh[0], fh[1]), pkbf2(fh[2], fh[3]));
        *(uint2*)(sbp + SM_ALO + nl * TSTRIDE + lane * 8) =
            make_uint2(pkbf2(fl[0], fl[1]), pkbf2(fl[2], fl[3]));
    }

    if (LAYER == 1 && tid < 64) {
        int r = row0 + tid;
        ((int*)(sbp + SM_IDX))[tid] = (r < N_NODES) ? __ldg(idx + r) : -1;
    }
    CP_WAIT0();
    __syncthreads();

    // ---- fragment addresses ----
    uint32_t aOff = (uint32_t)((mr + (lane & 15)) * TSTRIDE + (lane >> 4) * 16);
    uint32_t bOff = (uint32_t)((nc + (lane & 7) + ((lane >> 4) << 3)) * TSTRIDE +
                               ((lane >> 3) & 1) * 16);
    uint32_t uAhi = sb + SM_AHI + aOff;
    uint32_t uAlo = sb + SM_ALO + aOff;
    uint32_t uBhi = sb + SM_BHI + bOff;
    uint32_t uBlo = sb + SM_BLO + bOff;

    float acc[2][4][4];
    #pragma unroll
    for (int i = 0; i < 2; i++)
        #pragma unroll
        for (int j = 0; j < 4; j++)
            #pragma unroll
            for (int e = 0; e < 4; e++) acc[i][j][e] = 0.f;

    #pragma unroll
    for (int ks = 0; ks < 8; ks++) {
        uint32_t kbB = ks * 32;          // 16 bf16 = 32 bytes
        uint32_t ah[2][4], al[2][4];
        ldm_x4(ah[0], uAhi + kbB);
        ldm_x4(ah[1], uAhi + 16 * TSTRIDE + kbB);
        ldm_x4(al[0], uAlo + kbB);
        ldm_x4(al[1], uAlo + 16 * TSTRIDE + kbB);
        #pragma unroll
        for (int jp = 0; jp < 2; jp++) {
            uint32_t bh[4], bl[4];
            ldm_x4(bh, uBhi + jp * 16 * TSTRIDE + kbB);
            ldm_x4(bl, uBlo + jp * 16 * TSTRIDE + kbB);
            int j0 = 2 * jp;
            #pragma unroll
            for (int i = 0; i < 2; i++) {
                mma_bf16(acc[i][j0],     ah[i], bh);
                mma_bf16(acc[i][j0 + 1], ah[i], bh + 2);
                mma_bf16(acc[i][j0],     ah[i], bl);
                mma_bf16(acc[i][j0 + 1], ah[i], bl + 2);
                mma_bf16(acc[i][j0],     al[i], bh);
                mma_bf16(acc[i][j0 + 1], al[i], bh + 2);
            }
        }
    }

    // ---- epilogue ----
    int rq = lane >> 2;                  // 0..7
    int cp = 2 * (lane & 3);             // 0,2,4,6
    if (LAYER == 0) {
        #pragma unroll
        for (int i = 0; i < 2; i++) {
            #pragma unroll
            for (int j = 0; j < 4; j++) {
                int col = nc + j * 8 + cp;
                float2 b = __ldg((const float2*)(bias + col));
                int r1 = row0 + mr + i * 16 + rq;
                int r2 = r1 + 8;
                if (r1 < N_NODES) {
                    float2 v;
                    v.x = fmaxf(acc[i][j][0] + b.x, 0.f);
                    v.y = fmaxf(acc[i][j][1] + b.y, 0.f);
                    *(float2*)(g_bufB + (size_t)r1 * D + col) = v;
                }
                if (r2 < N_NODES) {
                    float2 v;
                    v.x = fmaxf(acc[i][j][2] + b.x, 0.f);
                    v.y = fmaxf(acc[i][j][3] + b.y, 0.f);
                    *(float2*)(g_bufB + (size_t)r2 * D + col) = v;
                }
            }
        }
    } else {
        __syncthreads();                 // about to overwrite A region
        float* sOutf = (float*)sbp;      // 64 rows x stride 132 floats
        #pragma unroll
        for (int i = 0; i < 2; i++) {
            #pragma unroll
            for (int j = 0; j < 4; j++) {
                int col = nc + j * 8 + cp;
                float2 b = __ldg((const float2*)(bias + col));
                int rl1 = mr + i * 16 + rq;
                float2 v1, v2;
                v1.x = acc[i][j][0] + b.x;  v1.y = acc[i][j][1] + b.y;
                v2.x = acc[i][j][2] + b.x;  v2.y = acc[i][j][3] + b.y;
                *(float2*)(sOutf + rl1 * 132 + col) = v1;
                *(float2*)(sOutf + (rl1 + 8) * 132 + col) = v2;
            }
        }
        __syncthreads();
        const int* sIdx = (const int*)(sbp + SM_IDX);
        int c    = tid & 127;
        int half = tid >> 7;
        int rs = half * 32, re = rs + 32;
        float accp = 0.f;
        int cur = -1;
        for (int r = rs; r < re; r++) {
            int g = sIdx[r];
            if (g != cur) {
                if (cur >= 0) atomicAdd(&g_pooled[cur * D + c], accp);
                accp = 0.f;
                cur = g;
            }
            if (g >= 0) accp += sOutf[r * 132 + c];
        }
        if (cur >= 0) atomicAdd(&g_pooled[cur * D + c], accp);
    }
}

// ---------------------------------------------------------------------------
// BatchNorm stats over the 512 graphs (two-pass)
// ---------------------------------------------------------------------------
__global__ void bn_stats(const float* __restrict__ gamma,
                         const float* __restrict__ beta) {
    int c = threadIdx.x;
    float s = 0.f;
    #pragma unroll 8
    for (int r = 0; r < N_GRAPHS; r++) s += g_pooled[r * D + c];
    float mean = s * (1.f / N_GRAPHS);
    float ss = 0.f;
    #pragma unroll 8
    for (int r = 0; r < N_GRAPHS; r++) {
        float d = g_pooled[r * D + c] - mean;
        ss += d * d;
    }
    float var = ss * (1.f / N_GRAPHS);
    float sc = rsqrtf(var + BN_EPS) * gamma[c];
    g_scale[c] = sc;
    g_shift[c] = beta[c] - mean * sc;
}

// ---------------------------------------------------------------------------
// Head: BN-apply, relu(@W3+b3), @W4+b4, log_softmax. One block per graph.
// ---------------------------------------------------------------------------
__global__ void head(const float* __restrict__ W3, const float* __restrict__ b3,
                     const float* __restrict__ W4, const float* __restrict__ b4,
                     float* __restrict__ out) {
    int g = blockIdx.x;
    int c = threadIdx.x;
    __shared__ float sNb[D];
    __shared__ float sZg[D];
    __shared__ float sL[N_CLASS];
    __shared__ float sLse;

    float p = g_pooled[g * D + c];
    sNb[c] = p * g_scale[c] + g_shift[c];
    __syncthreads();

    float acc = b3[c];
    #pragma unroll 8
    for (int k = 0; k < D; k++) acc = fmaf(sNb[k], W3[(size_t)k * D + c], acc);
    sZg[c] = fmaxf(acc, 0.f);
    __syncthreads();

    if (c < N_CLASS) {
        float l = b4[c];
        #pragma unroll 8
        for (int k = 0; k < D; k++) l = fmaf(sZg[k], W4[(size_t)k * N_CLASS + c], l);
        sL[c] = l;
    }
    __syncthreads();

    if (c == 0) {
        float m = sL[0];
        #pragma unroll
        for (int i = 1; i < N_CLASS; i++) m = fmaxf(m, sL[i]);
        float se = 0.f;
        #pragma unroll
        for (int i = 0; i < N_CLASS; i++) se += expf(sL[i] - m);
        sLse = m + logf(se);
    }
    __syncthreads();

    if (c < N_CLASS) out[g * N_CLASS + c] = sL[c] - sLse;
}

// ---------------------------------------------------------------------------
extern "C" void kernel_launch(void* const* d_in, const int* in_sizes, int n_in,
                              void* d_out, int out_size) {
    const float* x     = (const float*)d_in[0];
    const int*   ei    = (const int*)d_in[1];
    const int*   idx   = (const int*)d_in[2];
    const float* W1    = (const float*)d_in[3];
    const float* b1    = (const float*)d_in[4];
    const float* W2    = (const float*)d_in[5];
    const float* b2    = (const float*)d_in[6];
    const float* W3    = (const float*)d_in[7];
    const float* b3    = (const float*)d_in[8];
    const float* W4    = (const float*)d_in[9];
    const float* b4    = (const float*)d_in[10];
    const float* gamma = (const float*)d_in[11];
    const float* beta  = (const float*)d_in[12];
    float* out = (float*)d_out;

    const int* src = ei;
    const int* dst = ei + N_EDGES;

    __nv_bfloat16* whi_dev; __nv_bfloat16* wlo_dev;
    cudaGetSymbolAddress((void**)&whi_dev, g_Whi);
    cudaGetSymbolAddress((void**)&wlo_dev, g_Wlo);

    cudaFuncSetAttribute(fused_layer<0>, cudaFuncAttributeMaxDynamicSharedMemorySize, SMEM_MMA);
    cudaFuncSetAttribute(fused_layer<1>, cudaFuncAttributeMaxDynamicSharedMemorySize, SMEM_MMA);

    const int eBlocks  = (N_EDGES + 511) / 512;
    const int tcBlocks = PAD_M / 64;                // 1563

    // CSR build (once, serves both layers) + W prep
    prep0<<<(N_NODES + 255) / 256, 256>>>(W1, W2);
    hist_deg<<<eBlocks, 512>>>(dst);
    assign_rows<<<NSCAN, SCAN_BLK>>>();
    scatter_csr<<<eBlocks, 512>>>(src, dst);

    // fused layers: gather-agg + tensor-core GEMM + epilogue
    fused_layer<0><<<tcBlocks, 256, SMEM_MMA>>>(x, whi_dev, wlo_dev, b1, nullptr);
    fused_layer<1><<<tcBlocks, 256, SMEM_MMA>>>(nullptr, whi_dev + D * D, wlo_dev + D * D, b2, idx);

    // head
    bn_stats<<<1, 128>>>(gamma, beta);
    head<<<N_GRAPHS, 128>>>(W3, b3, W4, b4, out);
}

// round 14
// speedup vs baseline: 1.5820x; 1.5820x over previous
#include <cuda_runtime.h>
#include <cuda_bf16.h>
#include <math.h>
#include <stdint.h>

#define N_NODES  100000
#define N_EDGES  1600000
#define D        128
#define N_GRAPHS 512
#define N_CLASS  10
#define BN_EPS   1e-5f

#define NT   ((size_t)N_NODES * D)      // 12.8M floats
#define PAD_M 100032                    // 1563 * 64

#define SCAN_BLK 512
#define NSCAN    ((N_NODES + SCAN_BLK - 1) / SCAN_BLK)   // 196

// ---------------------------------------------------------------------------
// Scratch (allocation-free: __device__ globals)
// ---------------------------------------------------------------------------
__device__ float g_bufB[NT];            // z1 (fp32, gathered by agg pass 2)
__device__ __nv_bfloat16 g_Ahi[(size_t)PAD_M * D];   // pre-split agg output
__device__ __nv_bfloat16 g_Alo[(size_t)PAD_M * D];
__device__ float g_pooled[N_GRAPHS * D];
__device__ float g_scale[D];
__device__ float g_shift[D];

__device__ int g_deg[N_NODES];
__device__ int g_rowstart[N_NODES];
__device__ int g_cursor[N_NODES];
__device__ int g_csrsrc[N_EDGES];
__device__ int g_total;

// W split into bf16 hi/lo, n-major ([n][k]) — B operand for mma row.col
__device__ __nv_bfloat16 g_Whi[2][D * D];
__device__ __nv_bfloat16 g_Wlo[2][D * D];

// ---------------------------------------------------------------------------
// helpers
// ---------------------------------------------------------------------------
__device__ __forceinline__ uint32_t smem_to_u32(const void* p) {
    uint32_t a;
    asm("{ .reg .u64 t; cvta.to.shared.u64 t, %1; cvt.u32.u64 %0, t; }"
        : "=r"(a) : "l"(p));
    return a;
}
__device__ __forceinline__ void ldm_x4(uint32_t* r, uint32_t addr) {
    asm volatile("ldmatrix.sync.aligned.m8n8.x4.shared.b16 {%0,%1,%2,%3}, [%4];"
                 : "=r"(r[0]), "=r"(r[1]), "=r"(r[2]), "=r"(r[3]) : "r"(addr));
}
__device__ __forceinline__ void mma_bf16(float* c, const uint32_t* a,
                                         const uint32_t* b) {
    asm volatile(
        "mma.sync.aligned.m16n8k16.row.col.f32.bf16.bf16.f32 "
        "{%0,%1,%2,%3}, {%4,%5,%6,%7}, {%8,%9}, {%0,%1,%2,%3};"
        : "+f"(c[0]), "+f"(c[1]), "+f"(c[2]), "+f"(c[3])
        : "r"(a[0]), "r"(a[1]), "r"(a[2]), "r"(a[3]), "r"(b[0]), "r"(b[1]));
}
__device__ __forceinline__ uint32_t pkbf2(float a, float b) {
    __nv_bfloat162 t = __floats2bfloat162_rn(a, b);
    return *reinterpret_cast<uint32_t*>(&t);
}
__device__ __forceinline__ void cp16(uint32_t smem, const void* g) {
    asm volatile("cp.async.cg.shared.global [%0], [%1], 16;"
                 :: "r"(smem), "l"(g) : "memory");
}
#define CP_COMMIT() asm volatile("cp.async.commit_group;" ::: "memory")
#define CP_WAIT0()  asm volatile("cp.async.wait_group 0;" ::: "memory")

// ---------------------------------------------------------------------------
// prep0: zero deg/pooled/total + W hi/lo split (one kernel)
// ---------------------------------------------------------------------------
__global__ void prep0(const float* __restrict__ W1, const float* __restrict__ W2) {
    int i = blockIdx.x * blockDim.x + threadIdx.x;
    if (i < N_NODES) g_deg[i] = 0;
    if (i == 0) g_total = 0;
    if (i < N_GRAPHS * D) g_pooled[i] = 0.f;
    if (i < 2 * D * D) {
        int layer = i >> 14;
        int k = (i >> 7) & 127;
        int n = i & 127;
        float v = (layer ? W2 : W1)[k * D + n];
        __nv_bfloat16 hi = __float2bfloat16_rn(v);
        float lo = v - __bfloat162float(hi);
        g_Whi[layer][n * D + k] = hi;
        g_Wlo[layer][n * D + k] = __float2bfloat16_rn(lo);
    }
}

__global__ void hist_deg(const int* __restrict__ dst) {
    int e = blockIdx.x * blockDim.x + threadIdx.x;
    if (e < N_EDGES) atomicAdd(&g_deg[dst[e]], 1);
}

// Block-local inclusive scan + one global atomic per block. Segment order
// across blocks is arbitrary — irrelevant for gather correctness.
__global__ __launch_bounds__(SCAN_BLK) void assign_rows() {
    __shared__ int s[SCAN_BLK];
    __shared__ int sbase;
    int t = threadIdx.x;
    int i = blockIdx.x * SCAN_BLK + t;
    int v = (i < N_NODES) ? g_deg[i] : 0;
    s[t] = v;
    __syncthreads();
    #pragma unroll
    for (int off = 1; off < SCAN_BLK; off <<= 1) {
        int add = (t >= off) ? s[t - off] : 0;
        __syncthreads();
        s[t] += add;
        __syncthreads();
    }
    if (t == SCAN_BLK - 1) sbase = atomicAdd(&g_total, s[t]);
    __syncthreads();
    if (i < N_NODES) {
        int rs = sbase + s[t] - v;
        g_rowstart[i] = rs;
        g_cursor[i] = rs;
    }
}

__global__ void scatter_csr(const int* __restrict__ src,
                            const int* __restrict__ dst) {
    int e = blockIdx.x * blockDim.x + threadIdx.x;
    if (e < N_EDGES) {
        int pos = atomicAdd(&g_cursor[dst[e]], 1);
        g_csrsrc[pos] = src[e];
    }
}

// ---------------------------------------------------------------------------
// Gather aggregation + bf16 hi/lo split: writes g_Ahi/g_Alo (MMA-ready).
// One warp per (padded) node. SRC==0: gather x. SRC==1: gather g_bufB (z1).
// ---------------------------------------------------------------------------
template<int SRC>
__global__ __launch_bounds__(256)
void node_agg(const float* __restrict__ hext) {
    int n = blockIdx.x * 8 + (threadIdx.x >> 5);
    if (n >= PAD_M) return;
    int lane = threadIdx.x & 31;
    uint2* ohi = (uint2*)(g_Ahi + (size_t)n * D) + lane;
    uint2* olo = (uint2*)(g_Alo + (size_t)n * D) + lane;

    if (n >= N_NODES) {
        *ohi = make_uint2(0, 0);
        *olo = make_uint2(0, 0);
        return;
    }
    const float4* h4 = (const float4*)((SRC == 0) ? hext : (const float*)g_bufB);

    float4 acc  = __ldg(h4 + (size_t)n * 32 + lane);
    float4 acc2 = make_float4(0.f, 0.f, 0.f, 0.f);

    int s0 = g_rowstart[n];
    int e0 = s0 + g_deg[n];
    for (int base = s0; base < e0; base += 32) {
        int cnt = min(32, e0 - base);
        int sv = (lane < cnt) ? __ldg(g_csrsrc + base + lane) : 0;
        int j = 0;
        for (; j + 1 < cnt; j += 2) {
            int sa = __shfl_sync(0xffffffffu, sv, j);
            int sb = __shfl_sync(0xffffffffu, sv, j + 1);
            float4 va = __ldg(h4 + (size_t)sa * 32 + lane);
            float4 vb = __ldg(h4 + (size_t)sb * 32 + lane);
            acc.x += va.x;  acc.y += va.y;  acc.z += va.z;  acc.w += va.w;
            acc2.x += vb.x; acc2.y += vb.y; acc2.z += vb.z; acc2.w += vb.w;
        }
        if (j < cnt) {
            int sa = __shfl_sync(0xffffffffu, sv, j);
            float4 va = __ldg(h4 + (size_t)sa * 32 + lane);
            acc.x += va.x; acc.y += va.y; acc.z += va.z; acc.w += va.w;
        }
    }
    float f[4] = {acc.x + acc2.x, acc.y + acc2.y, acc.z + acc2.z, acc.w + acc2.w};
    float fh[4], fl[4];
    #pragma unroll
    for (int e = 0; e < 4; e++) {
        __nv_bfloat16 h = __float2bfloat16_rn(f[e]);
        fh[e] = __bfloat162float(h);
        fl[e] = f[e] - fh[e];
    }
    *ohi = make_uint2(pkbf2(fh[0], fh[1]), pkbf2(fh[2], fh[3]));
    *olo = make_uint2(pkbf2(fl[0], fl[1]), pkbf2(fl[2], fl[3]));
}

// ---------------------------------------------------------------------------
// Tensor-core GEMM via mma.sync (bf16 split-3, f32 accum).
// Block: 64 rows x 128 cols, 256 threads = 8 warps (2 m x 4 n), warp m32xn32.
// A pre-split (g_Ahi/g_Alo), staged via cp.async. 104.4KB smem -> 2 CTA/SM.
// MODE 0: relu(D + bias) -> g_bufB.  MODE 1: (D+bias) segment-pool -> g_pooled
// ---------------------------------------------------------------------------
#define TSTRIDE 272
#define SM_AHI 0
#define SM_ALO 17408
#define SM_BHI 34816
#define SM_BLO 69632
#define SM_IDX 104448
#define SMEM_MMA (104448 + 512)

template<int MODE>
__global__ __launch_bounds__(256, 2)
void gemm_mma(const __nv_bfloat16* __restrict__ Whi,
              const __nv_bfloat16* __restrict__ Wlo,
              const float* __restrict__ bias,
              const int* __restrict__ idx) {
    extern __shared__ __align__(16) char sbp[];
    uint32_t sb = smem_to_u32(sbp);

    int tid  = threadIdx.x;
    int wid  = tid >> 5;
    int lane = tid & 31;
    int row0 = blockIdx.x * 64;
    int mr = (wid >> 2) * 32;            // warp row base (0,32)
    int nc = (wid & 3) * 32;             // warp col base (0,32,64,96)

    // ---- stage A hi/lo (64 rows x 256B each) via cp.async ----
    #pragma unroll
    for (int q = 0; q < 4; q++) {
        int e = tid + q * 256;           // 0..1023
        int row = e >> 4;
        int ch  = e & 15;
        const __nv_bfloat16* gh = g_Ahi + (size_t)(row0 + row) * D + ch * 8;
        const __nv_bfloat16* gl = g_Alo + (size_t)(row0 + row) * D + ch * 8;
        cp16(sb + SM_AHI + row * TSTRIDE + ch * 16, gh);
        cp16(sb + SM_ALO + row * TSTRIDE + ch * 16, gl);
    }
    // ---- stage B hi/lo (128 rows x 256B each) via cp.async ----
    #pragma unroll
    for (int q = 0; q < 8; q++) {
        int e = tid + q * 256;           // 0..2047
        int row = e >> 4;
        int ch  = e & 15;
        cp16(sb + SM_BHI + row * TSTRIDE + ch * 16, Whi + row * D + ch * 8);
        cp16(sb + SM_BLO + row * TSTRIDE + ch * 16, Wlo + row * D + ch * 8);
    }
    CP_COMMIT();
    if (MODE == 1 && tid < 64) {
        int r = row0 + tid;
        ((int*)(sbp + SM_IDX))[tid] = (r < N_NODES) ? __ldg(idx + r) : -1;
    }
    CP_WAIT0();
    __syncthreads();

    // ---- fragment addresses ----
    uint32_t aOff = (uint32_t)((mr + (lane & 15)) * TSTRIDE + (lane >> 4) * 16);
    uint32_t bOff = (uint32_t)((nc + (lane & 7) + ((lane >> 4) << 3)) * TSTRIDE +
                               ((lane >> 3) & 1) * 16);
    uint32_t uAhi = sb + SM_AHI + aOff;
    uint32_t uAlo = sb + SM_ALO + aOff;
    uint32_t uBhi = sb + SM_BHI + bOff;
    uint32_t uBlo = sb + SM_BLO + bOff;

    float acc[2][4][4];
    #pragma unroll
    for (int i = 0; i < 2; i++)
        #pragma unroll
        for (int j = 0; j < 4; j++)
            #pragma unroll
            for (int e = 0; e < 4; e++) acc[i][j][e] = 0.f;

    #pragma unroll
    for (int ks = 0; ks < 8; ks++) {
        uint32_t kbB = ks * 32;          // 16 bf16 = 32 bytes
        uint32_t ah[2][4], al[2][4];
        ldm_x4(ah[0], uAhi + kbB);
        ldm_x4(ah[1], uAhi + 16 * TSTRIDE + kbB);
        ldm_x4(al[0], uAlo + kbB);
        ldm_x4(al[1], uAlo + 16 * TSTRIDE + kbB);
        #pragma unroll
        for (int jp = 0; jp < 2; jp++) {
            uint32_t bh[4], bl[4];
            ldm_x4(bh, uBhi + jp * 16 * TSTRIDE + kbB);
            ldm_x4(bl, uBlo + jp * 16 * TSTRIDE + kbB);
            int j0 = 2 * jp;
            #pragma unroll
            for (int i = 0; i < 2; i++) {
                mma_bf16(acc[i][j0],     ah[i], bh);
                mma_bf16(acc[i][j0 + 1], ah[i], bh + 2);
                mma_bf16(acc[i][j0],     ah[i], bl);
                mma_bf16(acc[i][j0 + 1], ah[i], bl + 2);
                mma_bf16(acc[i][j0],     al[i], bh);
                mma_bf16(acc[i][j0 + 1], al[i], bh + 2);
            }
        }
    }

    // ---- epilogue ----
    int rq = lane >> 2;                  // 0..7
    int cp = 2 * (lane & 3);             // 0,2,4,6
    if (MODE == 0) {
        #pragma unroll
        for (int i = 0; i < 2; i++) {
            #pragma unroll
            for (int j = 0; j < 4; j++) {
                int col = nc + j * 8 + cp;
                float2 b = __ldg((const float2*)(bias + col));
                int r1 = row0 + mr + i * 16 + rq;
                int r2 = r1 + 8;
                if (r1 < N_NODES) {
                    float2 v;
                    v.x = fmaxf(acc[i][j][0] + b.x, 0.f);
                    v.y = fmaxf(acc[i][j][1] + b.y, 0.f);
                    *(float2*)(g_bufB + (size_t)r1 * D + col) = v;
                }
                if (r2 < N_NODES) {
                    float2 v;
                    v.x = fmaxf(acc[i][j][2] + b.x, 0.f);
                    v.y = fmaxf(acc[i][j][3] + b.y, 0.f);
                    *(float2*)(g_bufB + (size_t)r2 * D + col) = v;
                }
            }
        }
    } else {
        __syncthreads();                 // about to overwrite A region
        float* sOutf = (float*)sbp;      // 64 rows x stride 132 floats
        #pragma unroll
        for (int i = 0; i < 2; i++) {
            #pragma unroll
            for (int j = 0; j < 4; j++) {
                int col = nc + j * 8 + cp;
                float2 b = __ldg((const float2*)(bias + col));
                int rl1 = mr + i * 16 + rq;
                float2 v1, v2;
                v1.x = acc[i][j][0] + b.x;  v1.y = acc[i][j][1] + b.y;
                v2.x = acc[i][j][2] + b.x;  v2.y = acc[i][j][3] + b.y;
                *(float2*)(sOutf + rl1 * 132 + col) = v1;
                *(float2*)(sOutf + (rl1 + 8) * 132 + col) = v2;
            }
        }
        __syncthreads();
        const int* sIdx = (const int*)(sbp + SM_IDX);
        int c    = tid & 127;
        int half = tid >> 7;
        int rs = half * 32, re = rs + 32;
        float accp = 0.f;
        int cur = -1;
        for (int r = rs; r < re; r++) {
            int g = sIdx[r];
            if (g != cur) {
                if (cur >= 0) atomicAdd(&g_pooled[cur * D + c], accp);
                accp = 0.f;
                cur = g;
            }
            if (g >= 0) accp += sOutf[r * 132 + c];
        }
        if (cur >= 0) atomicAdd(&g_pooled[cur * D + c], accp);
    }
}

// ---------------------------------------------------------------------------
// BatchNorm stats over the 512 graphs (two-pass)
// ---------------------------------------------------------------------------
__global__ void bn_stats(const float* __restrict__ gamma,
                         const float* __restrict__ beta) {
    int c = threadIdx.x;
    float s = 0.f;
    #pragma unroll 8
    for (int r = 0; r < N_GRAPHS; r++) s += g_pooled[r * D + c];
    float mean = s * (1.f / N_GRAPHS);
    float ss = 0.f;
    #pragma unroll 8
    for (int r = 0; r < N_GRAPHS; r++) {
        float d = g_pooled[r * D + c] - mean;
        ss += d * d;
    }
    float var = ss * (1.f / N_GRAPHS);
    float sc = rsqrtf(var + BN_EPS) * gamma[c];
    g_scale[c] = sc;
    g_shift[c] = beta[c] - mean * sc;
}

// ---------------------------------------------------------------------------
// Head: BN-apply, relu(@W3+b3), @W4+b4, log_softmax. One block per graph.
// ---------------------------------------------------------------------------
__global__ void head(const float* __restrict__ W3, const float* __restrict__ b3,
                     const float* __restrict__ W4, const float* __restrict__ b4,
                     float* __restrict__ out) {
    int g = blockIdx.x;
    int c = threadIdx.x;
    __shared__ float sNb[D];
    __shared__ float sZg[D];
    __shared__ float sL[N_CLASS];
    __shared__ float sLse;

    float p = g_pooled[g * D + c];
    sNb[c] = p * g_scale[c] + g_shift[c];
    __syncthreads();

    float acc = b3[c];
    #pragma unroll 8
    for (int k = 0; k < D; k++) acc = fmaf(sNb[k], W3[(size_t)k * D + c], acc);
    sZg[c] = fmaxf(acc, 0.f);
    __syncthreads();

    if (c < N_CLASS) {
        float l = b4[c];
        #pragma unroll 8
        for (int k = 0; k < D; k++) l = fmaf(sZg[k], W4[(size_t)k * N_CLASS + c], l);
        sL[c] = l;
    }
    __syncthreads();

    if (c == 0) {
        float m = sL[0];
        #pragma unroll
        for (int i = 1; i < N_CLASS; i++) m = fmaxf(m, sL[i]);
        float se = 0.f;
        #pragma unroll
        for (int i = 0; i < N_CLASS; i++) se += expf(sL[i] - m);
        sLse = m + logf(se);
    }
    __syncthreads();

    if (c < N_CLASS) out[g * N_CLASS + c] = sL[c] - sLse;
}

// ---------------------------------------------------------------------------
extern "C" void kernel_launch(void* const* d_in, const int* in_sizes, int n_in,
                              void* d_out, int out_size) {
    const float* x     = (const float*)d_in[0];
    const int*   ei    = (const int*)d_in[1];
    const int*   idx   = (const int*)d_in[2];
    const float* W1    = (const float*)d_in[3];
    const float* b1    = (const float*)d_in[4];
    const float* W2    = (const float*)d_in[5];
    const float* b2    = (const float*)d_in[6];
    const float* W3    = (const float*)d_in[7];
    const float* b3    = (const float*)d_in[8];
    const float* W4    = (const float*)d_in[9];
    const float* b4    = (const float*)d_in[10];
    const float* gamma = (const float*)d_in[11];
    const float* beta  = (const float*)d_in[12];
    float* out = (float*)d_out;

    const int* src = ei;
    const int* dst = ei + N_EDGES;

    __nv_bfloat16* whi_dev; __nv_bfloat16* wlo_dev;
    cudaGetSymbolAddress((void**)&whi_dev, g_Whi);
    cudaGetSymbolAddress((void**)&wlo_dev, g_Wlo);

    cudaFuncSetAttribute(gemm_mma<0>, cudaFuncAttributeMaxDynamicSharedMemorySize, SMEM_MMA);
    cudaFuncSetAttribute(gemm_mma<1>, cudaFuncAttributeMaxDynamicSharedMemorySize, SMEM_MMA);

    const int aggBlocks  = (PAD_M + 7) / 8;         // 12504
    const int eBlocks    = (N_EDGES + 511) / 512;
    const int tcBlocks   = PAD_M / 64;              // 1563

    // CSR build (once, serves both agg passes) + W prep
    prep0<<<(N_NODES + 255) / 256, 256>>>(W1, W2);
    hist_deg<<<eBlocks, 512>>>(dst);
    assign_rows<<<NSCAN, SCAN_BLK>>>();
    scatter_csr<<<eBlocks, 512>>>(src, dst);

    // layer 1
    node_agg<0><<<aggBlocks, 256>>>(x);
    gemm_mma<0><<<tcBlocks, 256, SMEM_MMA>>>(whi_dev, wlo_dev, b1, nullptr);

    // layer 2 + pooling
    node_agg<1><<<aggBlocks, 256>>>(nullptr);
    gemm_mma<1><<<tcBlocks, 256, SMEM_MMA>>>(whi_dev + D * D, wlo_dev + D * D, b2, idx);

    // head
    bn_stats<<<1, 128>>>(gamma, beta);
    head<<<N_GRAPHS, 128>>>(W3, b3, W4, b4, out);
}